// round 15
// baseline (speedup 1.0000x reference)
#include <cuda_runtime.h>
#include <cuda_fp16.h>
#include <math_constants.h>
#include <cstdint>

// ---------------------------------------------------------------------------
// CasualAttention via warp-level HMMA. B=4, S=2048, D=1024. compute_103 =>
// sm_80-class PTX (mma.sync / ldmatrix / cp.async).
//
// R15: correction products (hl, lh) accumulate in FP16 (mma f16.f16.f16.f16),
// hypothesized double-rate vs the f32-accumulator form. Dominant hh product
// stays f32-acc. Correction sums are ~0.01-0.5 with ~2e-4 increments, so f16
// accumulation contributes <=1e-5 relative error.
//   qkv    : hh (f32acc) + hl (f16acc)
//   scores : hh (f32acc) + hl + lh (f16acc)
//   av     : single product, f32acc (output precision)
// ---------------------------------------------------------------------------

static constexpr int Bb = 4;
static constexpr int S  = 2048;
static constexpr int D  = 1024;
static constexpr int M1 = Bb * S;          // 8192

__device__ __half g_xh[M1 * D];
__device__ __half g_wth[3 * D * D], g_wtl[3 * D * D];   // Wt[n][k]
__device__ __half g_qh[M1 * D], g_ql[M1 * D];
__device__ __half g_kh[M1 * D], g_kl[M1 * D];
__device__ __half g_vh[M1 * D];
__device__ float  g_p [(size_t)M1 * S];                 // fp32 scores
__device__ __half g_ph[(size_t)M1 * S];                 // softmax probs (fp16)

static constexpr int KCHUNK   = 32;
static constexpr int SLOT_B   = 128 * 80;               // 10240
static constexpr int STAGE_B  = 4 * SLOT_B;             // 40960
static constexpr int SMEM_BYTES = 2 * STAGE_B;          // 81920

// ---------------------------------------------------------------------------
__device__ __forceinline__ uint32_t smem_u32(const void* p) {
    uint32_t a;
    asm("{ .reg .u64 t; cvta.to.shared.u64 t, %1; cvt.u32.u64 %0, t; }"
        : "=r"(a) : "l"(p));
    return a;
}
__device__ __forceinline__ void cp16(uint32_t s, const void* g) {
    asm volatile("cp.async.cg.shared.global [%0], [%1], 16;\n" :: "r"(s), "l"(g));
}
__device__ __forceinline__ void cp_commit() {
    asm volatile("cp.async.commit_group;\n" ::: "memory");
}
__device__ __forceinline__ void ldsm4(uint32_t (&r)[4], uint32_t a) {
    asm volatile("ldmatrix.sync.aligned.m8n8.x4.shared.b16 {%0,%1,%2,%3}, [%4];"
                 : "=r"(r[0]), "=r"(r[1]), "=r"(r[2]), "=r"(r[3]) : "r"(a));
}
__device__ __forceinline__ void ldsm4t(uint32_t (&r)[4], uint32_t a) {
    asm volatile("ldmatrix.sync.aligned.m8n8.x4.trans.shared.b16 {%0,%1,%2,%3}, [%4];"
                 : "=r"(r[0]), "=r"(r[1]), "=r"(r[2]), "=r"(r[3]) : "r"(a));
}
// f32-accumulator HMMA
__device__ __forceinline__ void mma_f32a(float (&d)[4], const uint32_t (&a)[4],
                                         uint32_t b0, uint32_t b1) {
    asm volatile(
        "mma.sync.aligned.m16n8k16.row.col.f32.f16.f16.f32 "
        "{%0,%1,%2,%3}, {%4,%5,%6,%7}, {%8,%9}, {%0,%1,%2,%3};"
        : "+f"(d[0]), "+f"(d[1]), "+f"(d[2]), "+f"(d[3])
        : "r"(a[0]), "r"(a[1]), "r"(a[2]), "r"(a[3]), "r"(b0), "r"(b1));
}
// f16-accumulator HMMA (correction products)
__device__ __forceinline__ void mma_f16a(uint32_t (&d)[2], const uint32_t (&a)[4],
                                         uint32_t b0, uint32_t b1) {
    asm volatile(
        "mma.sync.aligned.m16n8k16.row.col.f16.f16.f16.f16 "
        "{%0,%1}, {%2,%3,%4,%5}, {%6,%7}, {%0,%1};"
        : "+r"(d[0]), "+r"(d[1])
        : "r"(a[0]), "r"(a[1]), "r"(a[2]), "r"(a[3]), "r"(b0), "r"(b1));
}

// ---------------------------------------------------------------------------
// cp.async tile loaders (K-chunk 32)
// ---------------------------------------------------------------------------
__device__ __forceinline__ void cpa_tile(uint32_t dst, const __half* __restrict__ src,
                                         int ld, int row0, int k0, int t) {
    #pragma unroll
    for (int it = 0; it < 2; it++) {
        int idx = t + it * 256;                 // 0..511
        int row = idx >> 2, u = idx & 3;        // 4 x 16B per row
        cp16(dst + row * 80 + u * 16, src + (size_t)(row0 + row) * ld + k0 + u * 8);
    }
}
__device__ __forceinline__ void cpa_tile_t(uint32_t dst, const __half* __restrict__ src,
                                           int ld, int k0, int n0, int t) {
    #pragma unroll
    for (int it = 0; it < 2; it++) {
        int idx = t + it * 256;
        int row = idx >> 4, u = idx & 15;       // 16 x 16B per row
        cp16(dst + row * 272 + u * 16, src + (size_t)(k0 + row) * ld + n0 + u * 8);
    }
}

// ---------------------------------------------------------------------------
// Compute one K-chunk (32). Warp tile 64x32 (wm=wid>>2, wn=wid&3).
// hh -> accF (f32). hl (BSPLIT) and lh (ASPLIT) -> accH (f16).
// ---------------------------------------------------------------------------
template <bool BTRANS, bool ASPLIT, bool BSPLIT>
__device__ __forceinline__ void compute_stage(uint32_t sb, int wid, int lane,
                                              float (&accF)[4][4][4],
                                              uint32_t (&accH)[4][4][2]) {
    const int wm = wid >> 2, wn = wid & 3;

    const uint32_t aRow = wm * 64 + (lane & 7) + ((lane >> 3) & 1) * 8;
    const uint32_t aCol = (lane >> 4) * 16;
    const uint32_t aH = sb + 0 * SLOT_B + aRow * 80 + aCol;
    const uint32_t aL = sb + 1 * SLOT_B + aRow * 80 + aCol;

    uint32_t bH, bL;
    if (!BTRANS) {      // B stored [n][k]
        const uint32_t bRow = wn * 32 + (lane & 7) + ((lane >> 4) & 1) * 8;
        const uint32_t bCol = ((lane >> 3) & 1) * 16;
        bH = sb + 2 * SLOT_B + bRow * 80 + bCol;
        bL = sb + 3 * SLOT_B + bRow * 80 + bCol;
    } else {            // B stored [k][n], ldmatrix.trans
        const uint32_t bRow = (lane & 7) + ((lane >> 3) & 1) * 8;
        const uint32_t bCol = wn * 64 + ((lane >> 4) & 1) * 16;
        bH = sb + 2 * SLOT_B + bRow * 272 + bCol;
        bL = sb + 3 * SLOT_B + bRow * 272 + bCol;
    }

    #pragma unroll
    for (int ks = 0; ks < 2; ks++) {
        uint32_t bh[2][4], bl[2][4];
        #pragma unroll
        for (int np = 0; np < 2; np++) {
            if (!BTRANS) {
                ldsm4(bh[np], bH + np * 16 * 80 + ks * 32);
                if (BSPLIT) ldsm4(bl[np], bL + np * 16 * 80 + ks * 32);
            } else {
                ldsm4t(bh[np], bH + np * 32 + ks * 16 * 272);
                if (BSPLIT) ldsm4t(bl[np], bL + np * 32 + ks * 16 * 272);
            }
        }
        #pragma unroll
        for (int ms = 0; ms < 4; ms++) {
            uint32_t ah[4], al[4];
            ldsm4(ah, aH + ms * 16 * 80 + ks * 32);
            if (ASPLIT) ldsm4(al, aL + ms * 16 * 80 + ks * 32);
            #pragma unroll
            for (int ns = 0; ns < 4; ns++)       // hh: f32 acc
                mma_f32a(accF[ms][ns], ah,
                         bh[ns >> 1][(ns & 1) * 2 + 0], bh[ns >> 1][(ns & 1) * 2 + 1]);
            if (BSPLIT)
                #pragma unroll
                for (int ns = 0; ns < 4; ns++)   // hl: f16 acc
                    mma_f16a(accH[ms][ns], ah,
                             bl[ns >> 1][(ns & 1) * 2 + 0], bl[ns >> 1][(ns & 1) * 2 + 1]);
            if (ASPLIT)
                #pragma unroll
                for (int ns = 0; ns < 4; ns++)   // lh: f16 acc
                    mma_f16a(accH[ms][ns], al,
                             bh[ns >> 1][(ns & 1) * 2 + 0], bh[ns >> 1][(ns & 1) * 2 + 1]);
        }
    }
}

// ---------------------------------------------------------------------------
// GEMM mainloop: 2-stage cp.async pipeline; merges f16 corrections at the end.
// ---------------------------------------------------------------------------
template <bool BTRANS, bool ASPLIT, bool BSPLIT>
__device__ __forceinline__ void gemm_main(
    const __half* __restrict__ Ah, const __half* __restrict__ Al, int lda, int m0,
    const __half* __restrict__ Bh, const __half* __restrict__ Bl, int ldb, int n0,
    int nchunks, float (&acc)[4][4][4], char* smem)
{
    const int t = threadIdx.x, wid = t >> 5, lane = t & 31;
    const uint32_t sb = smem_u32(smem);

    uint32_t accH[4][4][2];
    #pragma unroll
    for (int i = 0; i < 4; i++)
        #pragma unroll
        for (int j = 0; j < 4; j++) {
            #pragma unroll
            for (int e = 0; e < 4; e++) acc[i][j][e] = 0.f;
            accH[i][j][0] = 0u; accH[i][j][1] = 0u;   // +0,+0 in half2
        }

    auto issue = [&](int c) {
        const uint32_t st = sb + (c & 1) * STAGE_B;
        const int k0 = c * KCHUNK;
        cpa_tile(st, Ah, lda, m0, k0, t);
        if (ASPLIT) cpa_tile(st + SLOT_B, Al, lda, m0, k0, t);
        if (!BTRANS) {
            cpa_tile(st + 2 * SLOT_B, Bh, ldb, n0, k0, t);
            if (BSPLIT) cpa_tile(st + 3 * SLOT_B, Bl, ldb, n0, k0, t);
        } else {
            cpa_tile_t(st + 2 * SLOT_B, Bh, ldb, k0, n0, t);
            if (BSPLIT) cpa_tile_t(st + 3 * SLOT_B, Bl, ldb, k0, n0, t);
        }
        cp_commit();
    };

    issue(0);
    if (nchunks > 1) issue(1);

    for (int c = 0; c < nchunks; c++) {
        if (c + 1 < nchunks) asm volatile("cp.async.wait_group 1;\n" ::: "memory");
        else                 asm volatile("cp.async.wait_group 0;\n" ::: "memory");
        __syncthreads();
        compute_stage<BTRANS, ASPLIT, BSPLIT>(sb + (c & 1) * STAGE_B, wid, lane,
                                              acc, accH);
        __syncthreads();
        if (c + 2 < nchunks) issue(c + 2);
    }

    if (ASPLIT || BSPLIT) {
        #pragma unroll
        for (int i = 0; i < 4; i++)
            #pragma unroll
            for (int j = 0; j < 4; j++) {
                const __half2 p0 = *(const __half2*)&accH[i][j][0];
                const __half2 p1 = *(const __half2*)&accH[i][j][1];
                acc[i][j][0] += __low2float(p0);
                acc[i][j][1] += __high2float(p0);
                acc[i][j][2] += __low2float(p1);
                acc[i][j][3] += __high2float(p1);
            }
    }
}

// ---------------------------------------------------------------------------
// 0a) convert X -> fp16 hi
// ---------------------------------------------------------------------------
__global__ __launch_bounds__(256) void split_x(const float* __restrict__ X) {
    const int i = blockIdx.x * 256 + threadIdx.x;
    float4 v = ((const float4*)X)[i];
    float f[4] = {v.x, v.y, v.z, v.w};
    union { uint2 q; __half b[4]; } uh;
    #pragma unroll
    for (int e = 0; e < 4; e++) uh.b[e] = __float2half_rn(f[e]);
    *(uint2*)(g_xh + (size_t)i * 4) = uh.q;
}

// ---------------------------------------------------------------------------
// 0b) transpose + split W -> Wt[n][k] hi/lo fp16
// ---------------------------------------------------------------------------
__global__ __launch_bounds__(256) void transpose_w(const float* __restrict__ Wq,
                                                   const float* __restrict__ Wk,
                                                   const float* __restrict__ Wv) {
    const int which = blockIdx.z;
    const float* __restrict__ W = (which == 0) ? Wq : (which == 1) ? Wk : Wv;
    __shared__ float tile[32][33];
    const int n0 = blockIdx.x * 32, k0 = blockIdx.y * 32;
    const int tx = threadIdx.x & 31, ty = threadIdx.x >> 5;   // 32 x 8
    #pragma unroll
    for (int r = 0; r < 32; r += 8)
        tile[ty + r][tx] = W[(size_t)(k0 + ty + r) * D + n0 + tx];
    __syncthreads();
    #pragma unroll
    for (int r = 0; r < 32; r += 8) {
        float x = tile[tx][ty + r];
        __half h = __float2half_rn(x);
        __half l = __float2half_rn(x - __half2float(h));
        size_t o = (size_t)which * D * D + (size_t)(n0 + ty + r) * D + k0 + tx;
        g_wth[o] = h;
        g_wtl[o] = l;
    }
}

// ---------------------------------------------------------------------------
// 1) QKV GEMM: hh (f32acc) + hl (f16acc); epilogue -> Q/K hi+lo, V hi
// ---------------------------------------------------------------------------
extern __shared__ char dynsmem[];

__global__ __launch_bounds__(256) void qkv_gemm() {
    const int n0g = blockIdx.x * 128;
    const int m0  = blockIdx.y * 128;
    const int which = n0g >> 10;
    const int nW    = n0g & (D - 1);

    float acc[4][4][4];
    gemm_main<false, false, true>(g_xh, (const __half*)nullptr, D, m0,
                                  g_wth + (size_t)which * D * D,
                                  g_wtl + (size_t)which * D * D,
                                  D, nW, D / KCHUNK, acc, dynsmem);

    __half* __restrict__ Oh = (which == 0) ? g_qh : (which == 1) ? g_kh : g_vh;
    __half* __restrict__ Ol = (which == 0) ? g_ql : g_kl;   // unused for V
    const int wid = threadIdx.x >> 5, lane = threadIdx.x & 31;
    const int wm = wid >> 2, wn = wid & 3;
    #pragma unroll
    for (int ms = 0; ms < 4; ms++)
        #pragma unroll
        for (int ns = 0; ns < 4; ns++) {
            const int row = m0 + wm * 64 + ms * 16 + (lane >> 2);
            const int col = nW + wn * 32 + ns * 8 + (lane & 3) * 2;
            #pragma unroll
            for (int h = 0; h < 2; h++) {
                const float c0 = acc[ms][ns][2 * h + 0];
                const float c1 = acc[ms][ns][2 * h + 1];
                const __half h0 = __float2half_rn(c0), h1 = __float2half_rn(c1);
                const size_t o = (size_t)(row + 8 * h) * D + col;
                *(__half2*)(Oh + o) = __halves2half2(h0, h1);
                if (which != 2) {
                    const __half l0 = __float2half_rn(c0 - __half2float(h0));
                    const __half l1 = __float2half_rn(c1 - __half2float(h1));
                    *(__half2*)(Ol + o) = __halves2half2(l0, l1);
                }
            }
        }
}

// ---------------------------------------------------------------------------
// 2) scores GEMM: hh (f32acc) + hl + lh (f16acc); lower tiles only
// ---------------------------------------------------------------------------
__global__ __launch_bounds__(256) void scores_gemm() {
    const int jt = blockIdx.x, it = blockIdx.y, b = blockIdx.z;
    if (jt > it) return;
    const int m0 = it * 128, n0 = jt * 128;
    const size_t boff = (size_t)b * S * D;

    float acc[4][4][4];
    gemm_main<false, true, true>(g_qh + boff, g_ql + boff, D, m0,
                                 g_kh + boff, g_kl + boff, D, n0, D / KCHUNK,
                                 acc, dynsmem);

    float* __restrict__ P = g_p + (size_t)b * S * S;
    const float scale = 0.03125f;                  // 1/sqrt(1024)
    const int wid = threadIdx.x >> 5, lane = threadIdx.x & 31;
    const int wm = wid >> 2, wn = wid & 3;
    #pragma unroll
    for (int ms = 0; ms < 4; ms++)
        #pragma unroll
        for (int ns = 0; ns < 4; ns++) {
            const int row = m0 + wm * 64 + ms * 16 + (lane >> 2);
            const int col = n0 + wn * 32 + ns * 8 + (lane & 3) * 2;
            #pragma unroll
            for (int h = 0; h < 2; h++) {
                *(float2*)(P + (size_t)(row + 8 * h) * S + col) =
                    make_float2(acc[ms][ns][2 * h + 0] * scale,
                                acc[ms][ns][2 * h + 1] * scale);
            }
        }
}

// ---------------------------------------------------------------------------
// 3) causal softmax: g_p fp32 -> g_ph fp16 (zeros up to 128-aligned bound)
// ---------------------------------------------------------------------------
__global__ __launch_bounds__(256) void softmax_kernel() {
    const int r = blockIdx.x;                    // b*S + i
    const int i = r & (S - 1);
    const int jmax = ((i >> 7) + 1) << 7;        // AV reads only j < jmax
    const float* __restrict__ row = g_p + (size_t)r * S;
    const int t = threadIdx.x;

    float v[8];
    float mx = -CUDART_INF_F;
    #pragma unroll
    for (int k = 0; k < 8; k++) {
        const int j = t + k * 256;
        v[k] = (j <= i) ? row[j] : -CUDART_INF_F;
        mx = fmaxf(mx, v[k]);
    }
    __shared__ float red[256];
    red[t] = mx;
    __syncthreads();
    #pragma unroll
    for (int s = 128; s > 0; s >>= 1) {
        if (t < s) red[t] = fmaxf(red[t], red[t + s]);
        __syncthreads();
    }
    mx = red[0];
    __syncthreads();

    float sum = 0.f;
    #pragma unroll
    for (int k = 0; k < 8; k++) { v[k] = __expf(v[k] - mx); sum += v[k]; }
    red[t] = sum;
    __syncthreads();
    #pragma unroll
    for (int s = 128; s > 0; s >>= 1) {
        if (t < s) red[t] += red[t + s];
        __syncthreads();
    }
    const float inv = 1.0f / red[0];

    #pragma unroll
    for (int k = 0; k < 8; k++) {
        const int j = t + k * 256;
        if (j < jmax)
            g_ph[(size_t)r * S + j] = __float2half_rn(v[k] * inv);
    }
}

// ---------------------------------------------------------------------------
// 4) AV GEMM (1-product, f32acc): out = P @ Vh, causal K bound
// ---------------------------------------------------------------------------
__global__ __launch_bounds__(256, 2) void av_gemm(float* __restrict__ OutAll) {
    const int nt = blockIdx.x, mt = blockIdx.y, b = blockIdx.z;
    const int m0 = mt * 128, n0 = nt * 128;
    const int nchunks = (m0 + 128) / KCHUNK;     // causal bound

    float acc[4][4][4];
    gemm_main<true, false, false>(g_ph + (size_t)b * S * S, (const __half*)nullptr,
                                  S, m0,
                                  g_vh + (size_t)b * S * D, (const __half*)nullptr,
                                  D, n0, nchunks, acc, dynsmem);

    float* __restrict__ O = OutAll + (size_t)b * S * D;
    const int wid = threadIdx.x >> 5, lane = threadIdx.x & 31;
    const int wm = wid >> 2, wn = wid & 3;
    #pragma unroll
    for (int ms = 0; ms < 4; ms++)
        #pragma unroll
        for (int ns = 0; ns < 4; ns++) {
            const int row = m0 + wm * 64 + ms * 16 + (lane >> 2);
            const int col = n0 + wn * 32 + ns * 8 + (lane & 3) * 2;
            #pragma unroll
            for (int h = 0; h < 2; h++) {
                *(float2*)(O + (size_t)(row + 8 * h) * D + col) =
                    make_float2(acc[ms][ns][2 * h + 0], acc[ms][ns][2 * h + 1]);
            }
        }
}

// ---------------------------------------------------------------------------
extern "C" void kernel_launch(void* const* d_in, const int* in_sizes, int n_in,
                              void* d_out, int out_size)
{
    const float* x  = (const float*)d_in[0];
    const float* Wq = (const float*)d_in[1];
    const float* Wk = (const float*)d_in[2];
    const float* Wv = (const float*)d_in[3];
    float* out      = (float*)d_out;

    cudaFuncSetAttribute(qkv_gemm,    cudaFuncAttributeMaxDynamicSharedMemorySize, SMEM_BYTES);
    cudaFuncSetAttribute(scores_gemm, cudaFuncAttributeMaxDynamicSharedMemorySize, SMEM_BYTES);
    cudaFuncSetAttribute(av_gemm,     cudaFuncAttributeMaxDynamicSharedMemorySize, SMEM_BYTES);

    split_x<<<M1 * D / 4 / 256, 256>>>(x);
    transpose_w<<<dim3(D / 32, D / 32, 3), 256>>>(Wq, Wk, Wv);
    qkv_gemm<<<dim3(3 * D / 128, M1 / 128), 256, SMEM_BYTES>>>();
    scores_gemm<<<dim3(S / 128, S / 128, Bb), 256, SMEM_BYTES>>>();
    softmax_kernel<<<M1, 256>>>();
    av_gemm<<<dim3(D / 128, S / 128, Bb), 256, SMEM_BYTES>>>(out);
}

// round 16
// speedup vs baseline: 1.8320x; 1.8320x over previous
#include <cuda_runtime.h>
#include <cuda_fp16.h>
#include <math_constants.h>
#include <cstdint>

// ---------------------------------------------------------------------------
// CasualAttention, pure-fp16 operand chain on HMMA f32-acc (the fastest form
// measured; f16-acc regressed in R15). B=4, S=2048, D=1024.
// compute_103 => sm_80-class PTX (mma.sync / ldmatrix / cp.async).
//
// R16: ONE product per GEMM. Error budget (calibrated): X,W fp16 quant give
// Q/K/V err ~3.4e-4; scores of fp16 Q,K with fp32 acc adds ~0; P fp16 2.4e-4;
// total ~5.5-6.5e-4 < 1e-3.
//   qkv    : Q|K|V = Xh @ Wh      (fp32 acc)
//   scores : P = Qh Kh^T * scale  (fp32 acc, lower tiles only)
//   av     : out = P @ Vh         (fp32 acc, causal K bound)
// ---------------------------------------------------------------------------

static constexpr int Bb = 4;
static constexpr int S  = 2048;
static constexpr int D  = 1024;
static constexpr int M1 = Bb * S;          // 8192

__device__ __half g_x [M1 * D];
__device__ __half g_wt[3 * D * D];                      // Wt[n][k]
__device__ __half g_q [M1 * D];
__device__ __half g_k [M1 * D];
__device__ __half g_v [M1 * D];
__device__ float  g_p [(size_t)M1 * S];                 // fp32 scores
__device__ __half g_ph[(size_t)M1 * S];                 // softmax probs (fp16)

// smem: slot = [128 rows][32 fp16] pitch 80B (A / B-[n][k]) or [32 k-rows]
// [128 fp16] pitch 272B (B-trans, 8704B <= slot). 2 slots/stage, 2 stages.
static constexpr int KCHUNK   = 32;
static constexpr int SLOT_B   = 128 * 80;               // 10240
static constexpr int STAGE_B  = 2 * SLOT_B;             // 20480
static constexpr int SMEM_BYTES = 2 * STAGE_B;          // 40960

// ---------------------------------------------------------------------------
__device__ __forceinline__ uint32_t smem_u32(const void* p) {
    uint32_t a;
    asm("{ .reg .u64 t; cvta.to.shared.u64 t, %1; cvt.u32.u64 %0, t; }"
        : "=r"(a) : "l"(p));
    return a;
}
__device__ __forceinline__ void cp16(uint32_t s, const void* g) {
    asm volatile("cp.async.cg.shared.global [%0], [%1], 16;\n" :: "r"(s), "l"(g));
}
__device__ __forceinline__ void cp_commit() {
    asm volatile("cp.async.commit_group;\n" ::: "memory");
}
__device__ __forceinline__ void ldsm4(uint32_t (&r)[4], uint32_t a) {
    asm volatile("ldmatrix.sync.aligned.m8n8.x4.shared.b16 {%0,%1,%2,%3}, [%4];"
                 : "=r"(r[0]), "=r"(r[1]), "=r"(r[2]), "=r"(r[3]) : "r"(a));
}
__device__ __forceinline__ void ldsm4t(uint32_t (&r)[4], uint32_t a) {
    asm volatile("ldmatrix.sync.aligned.m8n8.x4.trans.shared.b16 {%0,%1,%2,%3}, [%4];"
                 : "=r"(r[0]), "=r"(r[1]), "=r"(r[2]), "=r"(r[3]) : "r"(a));
}
__device__ __forceinline__ void mma_f16(float (&d)[4], const uint32_t (&a)[4],
                                        uint32_t b0, uint32_t b1) {
    asm volatile(
        "mma.sync.aligned.m16n8k16.row.col.f32.f16.f16.f32 "
        "{%0,%1,%2,%3}, {%4,%5,%6,%7}, {%8,%9}, {%0,%1,%2,%3};"
        : "+f"(d[0]), "+f"(d[1]), "+f"(d[2]), "+f"(d[3])
        : "r"(a[0]), "r"(a[1]), "r"(a[2]), "r"(a[3]), "r"(b0), "r"(b1));
}

// ---------------------------------------------------------------------------
// cp.async tile loaders (K-chunk 32)
// ---------------------------------------------------------------------------
__device__ __forceinline__ void cpa_tile(uint32_t dst, const __half* __restrict__ src,
                                         int ld, int row0, int k0, int t) {
    #pragma unroll
    for (int it = 0; it < 2; it++) {
        int idx = t + it * 256;                 // 0..511
        int row = idx >> 2, u = idx & 3;        // 4 x 16B per row
        cp16(dst + row * 80 + u * 16, src + (size_t)(row0 + row) * ld + k0 + u * 8);
    }
}
__device__ __forceinline__ void cpa_tile_t(uint32_t dst, const __half* __restrict__ src,
                                           int ld, int k0, int n0, int t) {
    #pragma unroll
    for (int it = 0; it < 2; it++) {
        int idx = t + it * 256;
        int row = idx >> 4, u = idx & 15;       // 16 x 16B per row
        cp16(dst + row * 272 + u * 16, src + (size_t)(k0 + row) * ld + n0 + u * 8);
    }
}

// ---------------------------------------------------------------------------
// Compute one K-chunk (32). Warp tile 64x32 (wm=wid>>2, wn=wid&3). hh only.
// ---------------------------------------------------------------------------
template <bool BTRANS>
__device__ __forceinline__ void compute_stage(uint32_t sb, int wid, int lane,
                                              float (&acc)[4][4][4]) {
    const int wm = wid >> 2, wn = wid & 3;

    const uint32_t aRow = wm * 64 + (lane & 7) + ((lane >> 3) & 1) * 8;
    const uint32_t aCol = (lane >> 4) * 16;
    const uint32_t aH = sb + aRow * 80 + aCol;

    uint32_t bH;
    if (!BTRANS) {      // B stored [n][k]
        const uint32_t bRow = wn * 32 + (lane & 7) + ((lane >> 4) & 1) * 8;
        const uint32_t bCol = ((lane >> 3) & 1) * 16;
        bH = sb + SLOT_B + bRow * 80 + bCol;
    } else {            // B stored [k][n], ldmatrix.trans
        const uint32_t bRow = (lane & 7) + ((lane >> 3) & 1) * 8;
        const uint32_t bCol = wn * 64 + ((lane >> 4) & 1) * 16;
        bH = sb + SLOT_B + bRow * 272 + bCol;
    }

    #pragma unroll
    for (int ks = 0; ks < 2; ks++) {
        uint32_t bh[2][4];
        #pragma unroll
        for (int np = 0; np < 2; np++) {
            if (!BTRANS) ldsm4(bh[np], bH + np * 16 * 80 + ks * 32);
            else         ldsm4t(bh[np], bH + np * 32 + ks * 16 * 272);
        }
        #pragma unroll
        for (int ms = 0; ms < 4; ms++) {
            uint32_t ah[4];
            ldsm4(ah, aH + ms * 16 * 80 + ks * 32);
            #pragma unroll
            for (int ns = 0; ns < 4; ns++)
                mma_f16(acc[ms][ns], ah,
                        bh[ns >> 1][(ns & 1) * 2 + 0], bh[ns >> 1][(ns & 1) * 2 + 1]);
        }
    }
}

// ---------------------------------------------------------------------------
// GEMM mainloop: 2-stage cp.async pipeline over nchunks K-chunks of 32.
// ---------------------------------------------------------------------------
template <bool BTRANS>
__device__ __forceinline__ void gemm_main(
    const __half* __restrict__ A, int lda, int m0,
    const __half* __restrict__ B, int ldb, int n0,
    int nchunks, float (&acc)[4][4][4], char* smem)
{
    const int t = threadIdx.x, wid = t >> 5, lane = t & 31;
    const uint32_t sb = smem_u32(smem);

    #pragma unroll
    for (int i = 0; i < 4; i++)
        #pragma unroll
        for (int j = 0; j < 4; j++)
            #pragma unroll
            for (int e = 0; e < 4; e++) acc[i][j][e] = 0.f;

    auto issue = [&](int c) {
        const uint32_t st = sb + (c & 1) * STAGE_B;
        const int k0 = c * KCHUNK;
        cpa_tile(st, A, lda, m0, k0, t);
        if (!BTRANS) cpa_tile(st + SLOT_B, B, ldb, n0, k0, t);
        else         cpa_tile_t(st + SLOT_B, B, ldb, k0, n0, t);
        cp_commit();
    };

    issue(0);
    if (nchunks > 1) issue(1);

    for (int c = 0; c < nchunks; c++) {
        if (c + 1 < nchunks) asm volatile("cp.async.wait_group 1;\n" ::: "memory");
        else                 asm volatile("cp.async.wait_group 0;\n" ::: "memory");
        __syncthreads();
        compute_stage<BTRANS>(sb + (c & 1) * STAGE_B, wid, lane, acc);
        __syncthreads();
        if (c + 2 < nchunks) issue(c + 2);
    }
}

// ---------------------------------------------------------------------------
// 0a) convert X -> fp16
// ---------------------------------------------------------------------------
__global__ __launch_bounds__(256) void split_x(const float* __restrict__ X) {
    const int i = blockIdx.x * 256 + threadIdx.x;
    float4 v = ((const float4*)X)[i];
    float f[4] = {v.x, v.y, v.z, v.w};
    union { uint2 q; __half b[4]; } uh;
    #pragma unroll
    for (int e = 0; e < 4; e++) uh.b[e] = __float2half_rn(f[e]);
    *(uint2*)(g_x + (size_t)i * 4) = uh.q;
}

// ---------------------------------------------------------------------------
// 0b) transpose W -> Wt[n][k] fp16
// ---------------------------------------------------------------------------
__global__ __launch_bounds__(256) void transpose_w(const float* __restrict__ Wq,
                                                   const float* __restrict__ Wk,
                                                   const float* __restrict__ Wv) {
    const int which = blockIdx.z;
    const float* __restrict__ W = (which == 0) ? Wq : (which == 1) ? Wk : Wv;
    __shared__ float tile[32][33];
    const int n0 = blockIdx.x * 32, k0 = blockIdx.y * 32;
    const int tx = threadIdx.x & 31, ty = threadIdx.x >> 5;   // 32 x 8
    #pragma unroll
    for (int r = 0; r < 32; r += 8)
        tile[ty + r][tx] = W[(size_t)(k0 + ty + r) * D + n0 + tx];
    __syncthreads();
    #pragma unroll
    for (int r = 0; r < 32; r += 8) {
        float x = tile[tx][ty + r];
        size_t o = (size_t)which * D * D + (size_t)(n0 + ty + r) * D + k0 + tx;
        g_wt[o] = __float2half_rn(x);
    }
}

// ---------------------------------------------------------------------------
// 1) QKV GEMM (1 product): Q|K|V = Xh @ Wh
// ---------------------------------------------------------------------------
extern __shared__ char dynsmem[];

__global__ __launch_bounds__(256, 2) void qkv_gemm() {
    const int n0g = blockIdx.x * 128;
    const int m0  = blockIdx.y * 128;
    const int which = n0g >> 10;
    const int nW    = n0g & (D - 1);

    float acc[4][4][4];
    gemm_main<false>(g_x, D, m0, g_wt + (size_t)which * D * D, D, nW,
                     D / KCHUNK, acc, dynsmem);

    __half* __restrict__ Oh = (which == 0) ? g_q : (which == 1) ? g_k : g_v;
    const int wid = threadIdx.x >> 5, lane = threadIdx.x & 31;
    const int wm = wid >> 2, wn = wid & 3;
    #pragma unroll
    for (int ms = 0; ms < 4; ms++)
        #pragma unroll
        for (int ns = 0; ns < 4; ns++) {
            const int row = m0 + wm * 64 + ms * 16 + (lane >> 2);
            const int col = nW + wn * 32 + ns * 8 + (lane & 3) * 2;
            #pragma unroll
            for (int h = 0; h < 2; h++) {
                const __half h0 = __float2half_rn(acc[ms][ns][2 * h + 0]);
                const __half h1 = __float2half_rn(acc[ms][ns][2 * h + 1]);
                *(__half2*)(Oh + (size_t)(row + 8 * h) * D + col) =
                    __halves2half2(h0, h1);
            }
        }
}

// ---------------------------------------------------------------------------
// 2) scores GEMM (1 product): g_p = Q K^T * scale (lower tiles only)
// ---------------------------------------------------------------------------
__global__ __launch_bounds__(256, 2) void scores_gemm() {
    const int jt = blockIdx.x, it = blockIdx.y, b = blockIdx.z;
    if (jt > it) return;
    const int m0 = it * 128, n0 = jt * 128;
    const size_t boff = (size_t)b * S * D;

    float acc[4][4][4];
    gemm_main<false>(g_q + boff, D, m0, g_k + boff, D, n0, D / KCHUNK,
                     acc, dynsmem);

    float* __restrict__ P = g_p + (size_t)b * S * S;
    const float scale = 0.03125f;                  // 1/sqrt(1024)
    const int wid = threadIdx.x >> 5, lane = threadIdx.x & 31;
    const int wm = wid >> 2, wn = wid & 3;
    #pragma unroll
    for (int ms = 0; ms < 4; ms++)
        #pragma unroll
        for (int ns = 0; ns < 4; ns++) {
            const int row = m0 + wm * 64 + ms * 16 + (lane >> 2);
            const int col = n0 + wn * 32 + ns * 8 + (lane & 3) * 2;
            #pragma unroll
            for (int h = 0; h < 2; h++) {
                *(float2*)(P + (size_t)(row + 8 * h) * S + col) =
                    make_float2(acc[ms][ns][2 * h + 0] * scale,
                                acc[ms][ns][2 * h + 1] * scale);
            }
        }
}

// ---------------------------------------------------------------------------
// 3) causal softmax: g_p fp32 -> g_ph fp16 (zeros up to 128-aligned bound)
// ---------------------------------------------------------------------------
__global__ __launch_bounds__(256) void softmax_kernel() {
    const int r = blockIdx.x;                    // b*S + i
    const int i = r & (S - 1);
    const int jmax = ((i >> 7) + 1) << 7;        // AV reads only j < jmax
    const float* __restrict__ row = g_p + (size_t)r * S;
    const int t = threadIdx.x;

    float v[8];
    float mx = -CUDART_INF_F;
    #pragma unroll
    for (int k = 0; k < 8; k++) {
        const int j = t + k * 256;
        v[k] = (j <= i) ? row[j] : -CUDART_INF_F;
        mx = fmaxf(mx, v[k]);
    }
    __shared__ float red[256];
    red[t] = mx;
    __syncthreads();
    #pragma unroll
    for (int s = 128; s > 0; s >>= 1) {
        if (t < s) red[t] = fmaxf(red[t], red[t + s]);
        __syncthreads();
    }
    mx = red[0];
    __syncthreads();

    float sum = 0.f;
    #pragma unroll
    for (int k = 0; k < 8; k++) { v[k] = __expf(v[k] - mx); sum += v[k]; }
    red[t] = sum;
    __syncthreads();
    #pragma unroll
    for (int s = 128; s > 0; s >>= 1) {
        if (t < s) red[t] += red[t + s];
        __syncthreads();
    }
    const float inv = 1.0f / red[0];

    #pragma unroll
    for (int k = 0; k < 8; k++) {
        const int j = t + k * 256;
        if (j < jmax)
            g_ph[(size_t)r * S + j] = __float2half_rn(v[k] * inv);
    }
}

// ---------------------------------------------------------------------------
// 4) AV GEMM (1 product): out = P @ Vh, causal K bound
// ---------------------------------------------------------------------------
__global__ __launch_bounds__(256, 2) void av_gemm(float* __restrict__ OutAll) {
    const int nt = blockIdx.x, mt = blockIdx.y, b = blockIdx.z;
    const int m0 = mt * 128, n0 = nt * 128;
    const int nchunks = (m0 + 128) / KCHUNK;     // causal bound

    float acc[4][4][4];
    gemm_main<true>(g_ph + (size_t)b * S * S, S, m0,
                    g_v + (size_t)b * S * D, D, n0, nchunks, acc, dynsmem);

    float* __restrict__ O = OutAll + (size_t)b * S * D;
    const int wid = threadIdx.x >> 5, lane = threadIdx.x & 31;
    const int wm = wid >> 2, wn = wid & 3;
    #pragma unroll
    for (int ms = 0; ms < 4; ms++)
        #pragma unroll
        for (int ns = 0; ns < 4; ns++) {
            const int row = m0 + wm * 64 + ms * 16 + (lane >> 2);
            const int col = n0 + wn * 32 + ns * 8 + (lane & 3) * 2;
            #pragma unroll
            for (int h = 0; h < 2; h++) {
                *(float2*)(O + (size_t)(row + 8 * h) * D + col) =
                    make_float2(acc[ms][ns][2 * h + 0], acc[ms][ns][2 * h + 1]);
            }
        }
}

// ---------------------------------------------------------------------------
extern "C" void kernel_launch(void* const* d_in, const int* in_sizes, int n_in,
                              void* d_out, int out_size)
{
    const float* x  = (const float*)d_in[0];
    const float* Wq = (const float*)d_in[1];
    const float* Wk = (const float*)d_in[2];
    const float* Wv = (const float*)d_in[3];
    float* out      = (float*)d_out;

    cudaFuncSetAttribute(qkv_gemm,    cudaFuncAttributeMaxDynamicSharedMemorySize, SMEM_BYTES);
    cudaFuncSetAttribute(scores_gemm, cudaFuncAttributeMaxDynamicSharedMemorySize, SMEM_BYTES);
    cudaFuncSetAttribute(av_gemm,     cudaFuncAttributeMaxDynamicSharedMemorySize, SMEM_BYTES);

    split_x<<<M1 * D / 4 / 256, 256>>>(x);
    transpose_w<<<dim3(D / 32, D / 32, 3), 256>>>(Wq, Wk, Wv);
    qkv_gemm<<<dim3(3 * D / 128, M1 / 128), 256, SMEM_BYTES>>>();
    scores_gemm<<<dim3(S / 128, S / 128, Bb), 256, SMEM_BYTES>>>();
    softmax_kernel<<<M1, 256>>>();
    av_gemm<<<dim3(D / 128, S / 128, Bb), 256, SMEM_BYTES>>>(out);
}

// round 17
// speedup vs baseline: 2.0993x; 1.1459x over previous
#include <cuda_runtime.h>
#include <cuda_fp16.h>
#include <math_constants.h>
#include <cstdint>

// ---------------------------------------------------------------------------
// CasualAttention, pure-fp16 operand chain on HMMA f32-acc. B=4,S=2048,D=1024.
// compute_103 => sm_80-class PTX (mma.sync / ldmatrix / cp.async).
//
// R17: KCHUNK back to 64 (pitch-144 A slots, pitch-272 B-trans slots, as
// validated in R12) to restore MMA density per barrier: R16's KCHUNK=32 cut
// tensor% to 41.6 because barriers/cp.async overhead per chunk stayed fixed
// while MMAs per chunk dropped 3x. 2 slots/stage, 2 stages = 73.7KB -> still
// 2 CTAs/SM.
//   qkv    : Q|K|V = Xh @ Wh      (fp32 acc)
//   scores : P = Qh Kh^T * scale  (fp32 acc, lower tiles only)
//   av     : out = P @ Vh         (fp32 acc, causal K bound)
// ---------------------------------------------------------------------------

static constexpr int Bb = 4;
static constexpr int S  = 2048;
static constexpr int D  = 1024;
static constexpr int M1 = Bb * S;          // 8192

__device__ __half g_x [M1 * D];
__device__ __half g_wt[3 * D * D];                      // Wt[n][k]
__device__ __half g_q [M1 * D];
__device__ __half g_k [M1 * D];
__device__ __half g_v [M1 * D];
__device__ float  g_p [(size_t)M1 * S];                 // fp32 scores
__device__ __half g_ph[(size_t)M1 * S];                 // softmax probs (fp16)

// smem: slot = [128 rows][64 fp16] pitch 144B (A / B-[n][k]) or [64 k-rows]
// [128 fp16] pitch 272B (B-trans, 17408B <= 18432B slot). 2 slots/stage.
static constexpr int KCHUNK   = 64;
static constexpr int SLOT_B   = 128 * 144;              // 18432
static constexpr int STAGE_B  = 2 * SLOT_B;             // 36864
static constexpr int SMEM_BYTES = 2 * STAGE_B;          // 73728 -> 2 CTAs/SM

// ---------------------------------------------------------------------------
__device__ __forceinline__ uint32_t smem_u32(const void* p) {
    uint32_t a;
    asm("{ .reg .u64 t; cvta.to.shared.u64 t, %1; cvt.u32.u64 %0, t; }"
        : "=r"(a) : "l"(p));
    return a;
}
__device__ __forceinline__ void cp16(uint32_t s, const void* g) {
    asm volatile("cp.async.cg.shared.global [%0], [%1], 16;\n" :: "r"(s), "l"(g));
}
__device__ __forceinline__ void cp_commit() {
    asm volatile("cp.async.commit_group;\n" ::: "memory");
}
__device__ __forceinline__ void ldsm4(uint32_t (&r)[4], uint32_t a) {
    asm volatile("ldmatrix.sync.aligned.m8n8.x4.shared.b16 {%0,%1,%2,%3}, [%4];"
                 : "=r"(r[0]), "=r"(r[1]), "=r"(r[2]), "=r"(r[3]) : "r"(a));
}
__device__ __forceinline__ void ldsm4t(uint32_t (&r)[4], uint32_t a) {
    asm volatile("ldmatrix.sync.aligned.m8n8.x4.trans.shared.b16 {%0,%1,%2,%3}, [%4];"
                 : "=r"(r[0]), "=r"(r[1]), "=r"(r[2]), "=r"(r[3]) : "r"(a));
}
__device__ __forceinline__ void mma_f16(float (&d)[4], const uint32_t (&a)[4],
                                        uint32_t b0, uint32_t b1) {
    asm volatile(
        "mma.sync.aligned.m16n8k16.row.col.f32.f16.f16.f32 "
        "{%0,%1,%2,%3}, {%4,%5,%6,%7}, {%8,%9}, {%0,%1,%2,%3};"
        : "+f"(d[0]), "+f"(d[1]), "+f"(d[2]), "+f"(d[3])
        : "r"(a[0]), "r"(a[1]), "r"(a[2]), "r"(a[3]), "r"(b0), "r"(b1));
}

// ---------------------------------------------------------------------------
// cp.async tile loaders (K-chunk 64)
// ---------------------------------------------------------------------------
// [128 rows][64 fp16] pitch 144
__device__ __forceinline__ void cpa_tile(uint32_t dst, const __half* __restrict__ src,
                                         int ld, int row0, int k0, int t) {
    #pragma unroll
    for (int it = 0; it < 4; it++) {
        int idx = t + it * 256;                 // 0..1023
        int row = idx >> 3, u = idx & 7;        // 8 x 16B per row
        cp16(dst + row * 144 + u * 16, src + (size_t)(row0 + row) * ld + k0 + u * 8);
    }
}
// [64 k-rows][128 fp16] pitch 272
__device__ __forceinline__ void cpa_tile_t(uint32_t dst, const __half* __restrict__ src,
                                           int ld, int k0, int n0, int t) {
    #pragma unroll
    for (int it = 0; it < 4; it++) {
        int idx = t + it * 256;
        int row = idx >> 4, u = idx & 15;       // 16 x 16B per row
        cp16(dst + row * 272 + u * 16, src + (size_t)(k0 + row) * ld + n0 + u * 8);
    }
}

// ---------------------------------------------------------------------------
// Compute one K-chunk (64). Warp tile 64x32 (wm=wid>>2, wn=wid&3).
// ---------------------------------------------------------------------------
template <bool BTRANS>
__device__ __forceinline__ void compute_stage(uint32_t sb, int wid, int lane,
                                              float (&acc)[4][4][4]) {
    const int wm = wid >> 2, wn = wid & 3;

    const uint32_t aRow = wm * 64 + (lane & 7) + ((lane >> 3) & 1) * 8;
    const uint32_t aCol = (lane >> 4) * 16;
    const uint32_t aH = sb + aRow * 144 + aCol;

    uint32_t bH;
    if (!BTRANS) {      // B stored [n][k]
        const uint32_t bRow = wn * 32 + (lane & 7) + ((lane >> 4) & 1) * 8;
        const uint32_t bCol = ((lane >> 3) & 1) * 16;
        bH = sb + SLOT_B + bRow * 144 + bCol;
    } else {            // B stored [k][n], ldmatrix.trans
        const uint32_t bRow = (lane & 7) + ((lane >> 3) & 1) * 8;
        const uint32_t bCol = wn * 64 + ((lane >> 4) & 1) * 16;
        bH = sb + SLOT_B + bRow * 272 + bCol;
    }

    #pragma unroll
    for (int ks = 0; ks < 4; ks++) {
        uint32_t bh[2][4];
        #pragma unroll
        for (int np = 0; np < 2; np++) {
            if (!BTRANS) ldsm4(bh[np], bH + np * 16 * 144 + ks * 32);
            else         ldsm4t(bh[np], bH + np * 32 + ks * 16 * 272);
        }
        #pragma unroll
        for (int ms = 0; ms < 4; ms++) {
            uint32_t ah[4];
            ldsm4(ah, aH + ms * 16 * 144 + ks * 32);
            #pragma unroll
            for (int ns = 0; ns < 4; ns++)
                mma_f16(acc[ms][ns], ah,
                        bh[ns >> 1][(ns & 1) * 2 + 0], bh[ns >> 1][(ns & 1) * 2 + 1]);
        }
    }
}

// ---------------------------------------------------------------------------
// GEMM mainloop: 2-stage cp.async pipeline over nchunks K-chunks of 64.
// ---------------------------------------------------------------------------
template <bool BTRANS>
__device__ __forceinline__ void gemm_main(
    const __half* __restrict__ A, int lda, int m0,
    const __half* __restrict__ B, int ldb, int n0,
    int nchunks, float (&acc)[4][4][4], char* smem)
{
    const int t = threadIdx.x, wid = t >> 5, lane = t & 31;
    const uint32_t sb = smem_u32(smem);

    #pragma unroll
    for (int i = 0; i < 4; i++)
        #pragma unroll
        for (int j = 0; j < 4; j++)
            #pragma unroll
            for (int e = 0; e < 4; e++) acc[i][j][e] = 0.f;

    auto issue = [&](int c) {
        const uint32_t st = sb + (c & 1) * STAGE_B;
        const int k0 = c * KCHUNK;
        cpa_tile(st, A, lda, m0, k0, t);
        if (!BTRANS) cpa_tile(st + SLOT_B, B, ldb, n0, k0, t);
        else         cpa_tile_t(st + SLOT_B, B, ldb, k0, n0, t);
        cp_commit();
    };

    issue(0);
    if (nchunks > 1) issue(1);

    for (int c = 0; c < nchunks; c++) {
        if (c + 1 < nchunks) asm volatile("cp.async.wait_group 1;\n" ::: "memory");
        else                 asm volatile("cp.async.wait_group 0;\n" ::: "memory");
        __syncthreads();
        compute_stage<BTRANS>(sb + (c & 1) * STAGE_B, wid, lane, acc);
        __syncthreads();
        if (c + 2 < nchunks) issue(c + 2);
    }
}

// ---------------------------------------------------------------------------
// 0a) convert X -> fp16
// ---------------------------------------------------------------------------
__global__ __launch_bounds__(256) void split_x(const float* __restrict__ X) {
    const int i = blockIdx.x * 256 + threadIdx.x;
    float4 v = ((const float4*)X)[i];
    float f[4] = {v.x, v.y, v.z, v.w};
    union { uint2 q; __half b[4]; } uh;
    #pragma unroll
    for (int e = 0; e < 4; e++) uh.b[e] = __float2half_rn(f[e]);
    *(uint2*)(g_x + (size_t)i * 4) = uh.q;
}

// ---------------------------------------------------------------------------
// 0b) transpose W -> Wt[n][k] fp16
// ---------------------------------------------------------------------------
__global__ __launch_bounds__(256) void transpose_w(const float* __restrict__ Wq,
                                                   const float* __restrict__ Wk,
                                                   const float* __restrict__ Wv) {
    const int which = blockIdx.z;
    const float* __restrict__ W = (which == 0) ? Wq : (which == 1) ? Wk : Wv;
    __shared__ float tile[32][33];
    const int n0 = blockIdx.x * 32, k0 = blockIdx.y * 32;
    const int tx = threadIdx.x & 31, ty = threadIdx.x >> 5;   // 32 x 8
    #pragma unroll
    for (int r = 0; r < 32; r += 8)
        tile[ty + r][tx] = W[(size_t)(k0 + ty + r) * D + n0 + tx];
    __syncthreads();
    #pragma unroll
    for (int r = 0; r < 32; r += 8) {
        float x = tile[tx][ty + r];
        size_t o = (size_t)which * D * D + (size_t)(n0 + ty + r) * D + k0 + tx;
        g_wt[o] = __float2half_rn(x);
    }
}

// ---------------------------------------------------------------------------
// 1) QKV GEMM (1 product): Q|K|V = Xh @ Wh
// ---------------------------------------------------------------------------
extern __shared__ char dynsmem[];

__global__ __launch_bounds__(256, 2) void qkv_gemm() {
    const int n0g = blockIdx.x * 128;
    const int m0  = blockIdx.y * 128;
    const int which = n0g >> 10;
    const int nW    = n0g & (D - 1);

    float acc[4][4][4];
    gemm_main<false>(g_x, D, m0, g_wt + (size_t)which * D * D, D, nW,
                     D / KCHUNK, acc, dynsmem);

    __half* __restrict__ Oh = (which == 0) ? g_q : (which == 1) ? g_k : g_v;
    const int wid = threadIdx.x >> 5, lane = threadIdx.x & 31;
    const int wm = wid >> 2, wn = wid & 3;
    #pragma unroll
    for (int ms = 0; ms < 4; ms++)
        #pragma unroll
        for (int ns = 0; ns < 4; ns++) {
            const int row = m0 + wm * 64 + ms * 16 + (lane >> 2);
            const int col = nW + wn * 32 + ns * 8 + (lane & 3) * 2;
            #pragma unroll
            for (int h = 0; h < 2; h++) {
                const __half h0 = __float2half_rn(acc[ms][ns][2 * h + 0]);
                const __half h1 = __float2half_rn(acc[ms][ns][2 * h + 1]);
                *(__half2*)(Oh + (size_t)(row + 8 * h) * D + col) =
                    __halves2half2(h0, h1);
            }
        }
}

// ---------------------------------------------------------------------------
// 2) scores GEMM (1 product): g_p = Q K^T * scale (lower tiles only)
// ---------------------------------------------------------------------------
__global__ __launch_bounds__(256, 2) void scores_gemm() {
    const int jt = blockIdx.x, it = blockIdx.y, b = blockIdx.z;
    if (jt > it) return;
    const int m0 = it * 128, n0 = jt * 128;
    const size_t boff = (size_t)b * S * D;

    float acc[4][4][4];
    gemm_main<false>(g_q + boff, D, m0, g_k + boff, D, n0, D / KCHUNK,
                     acc, dynsmem);

    float* __restrict__ P = g_p + (size_t)b * S * S;
    const float scale = 0.03125f;                  // 1/sqrt(1024)
    const int wid = threadIdx.x >> 5, lane = threadIdx.x & 31;
    const int wm = wid >> 2, wn = wid & 3;
    #pragma unroll
    for (int ms = 0; ms < 4; ms++)
        #pragma unroll
        for (int ns = 0; ns < 4; ns++) {
            const int row = m0 + wm * 64 + ms * 16 + (lane >> 2);
            const int col = n0 + wn * 32 + ns * 8 + (lane & 3) * 2;
            #pragma unroll
            for (int h = 0; h < 2; h++) {
                *(float2*)(P + (size_t)(row + 8 * h) * S + col) =
                    make_float2(acc[ms][ns][2 * h + 0] * scale,
                                acc[ms][ns][2 * h + 1] * scale);
            }
        }
}

// ---------------------------------------------------------------------------
// 3) causal softmax: g_p fp32 -> g_ph fp16 (zeros up to 128-aligned bound)
// ---------------------------------------------------------------------------
__global__ __launch_bounds__(256) void softmax_kernel() {
    const int r = blockIdx.x;                    // b*S + i
    const int i = r & (S - 1);
    const int jmax = ((i >> 7) + 1) << 7;        // AV reads only j < jmax
    const float* __restrict__ row = g_p + (size_t)r * S;
    const int t = threadIdx.x;

    float v[8];
    float mx = -CUDART_INF_F;
    #pragma unroll
    for (int k = 0; k < 8; k++) {
        const int j = t + k * 256;
        v[k] = (j <= i) ? row[j] : -CUDART_INF_F;
        mx = fmaxf(mx, v[k]);
    }
    __shared__ float red[256];
    red[t] = mx;
    __syncthreads();
    #pragma unroll
    for (int s = 128; s > 0; s >>= 1) {
        if (t < s) red[t] = fmaxf(red[t], red[t + s]);
        __syncthreads();
    }
    mx = red[0];
    __syncthreads();

    float sum = 0.f;
    #pragma unroll
    for (int k = 0; k < 8; k++) { v[k] = __expf(v[k] - mx); sum += v[k]; }
    red[t] = sum;
    __syncthreads();
    #pragma unroll
    for (int s = 128; s > 0; s >>= 1) {
        if (t < s) red[t] += red[t + s];
        __syncthreads();
    }
    const float inv = 1.0f / red[0];

    #pragma unroll
    for (int k = 0; k < 8; k++) {
        const int j = t + k * 256;
        if (j < jmax)
            g_ph[(size_t)r * S + j] = __float2half_rn(v[k] * inv);
    }
}

// ---------------------------------------------------------------------------
// 4) AV GEMM (1 product): out = P @ Vh, causal K bound
// ---------------------------------------------------------------------------
__global__ __launch_bounds__(256, 2) void av_gemm(float* __restrict__ OutAll) {
    const int nt = blockIdx.x, mt = blockIdx.y, b = blockIdx.z;
    const int m0 = mt * 128, n0 = nt * 128;
    const int nchunks = (m0 + 128) / KCHUNK;     // causal bound

    float acc[4][4][4];
    gemm_main<true>(g_ph + (size_t)b * S * S, S, m0,
                    g_v + (size_t)b * S * D, D, n0, nchunks, acc, dynsmem);

    float* __restrict__ O = OutAll + (size_t)b * S * D;
    const int wid = threadIdx.x >> 5, lane = threadIdx.x & 31;
    const int wm = wid >> 2, wn = wid & 3;
    #pragma unroll
    for (int ms = 0; ms < 4; ms++)
        #pragma unroll
        for (int ns = 0; ns < 4; ns++) {
            const int row = m0 + wm * 64 + ms * 16 + (lane >> 2);
            const int col = n0 + wn * 32 + ns * 8 + (lane & 3) * 2;
            #pragma unroll
            for (int h = 0; h < 2; h++) {
                *(float2*)(O + (size_t)(row + 8 * h) * D + col) =
                    make_float2(acc[ms][ns][2 * h + 0], acc[ms][ns][2 * h + 1]);
            }
        }
}

// ---------------------------------------------------------------------------
extern "C" void kernel_launch(void* const* d_in, const int* in_sizes, int n_in,
                              void* d_out, int out_size)
{
    const float* x  = (const float*)d_in[0];
    const float* Wq = (const float*)d_in[1];
    const float* Wk = (const float*)d_in[2];
    const float* Wv = (const float*)d_in[3];
    float* out      = (float*)d_out;

    cudaFuncSetAttribute(qkv_gemm,    cudaFuncAttributeMaxDynamicSharedMemorySize, SMEM_BYTES);
    cudaFuncSetAttribute(scores_gemm, cudaFuncAttributeMaxDynamicSharedMemorySize, SMEM_BYTES);
    cudaFuncSetAttribute(av_gemm,     cudaFuncAttributeMaxDynamicSharedMemorySize, SMEM_BYTES);

    split_x<<<M1 * D / 4 / 256, 256>>>(x);
    transpose_w<<<dim3(D / 32, D / 32, 3), 256>>>(Wq, Wk, Wv);
    qkv_gemm<<<dim3(3 * D / 128, M1 / 128), 256, SMEM_BYTES>>>();
    scores_gemm<<<dim3(S / 128, S / 128, Bb), 256, SMEM_BYTES>>>();
    softmax_kernel<<<M1, 256>>>();
    av_gemm<<<dim3(D / 128, S / 128, Bb), 256, SMEM_BYTES>>>(out);
}